// round 1
// baseline (speedup 1.0000x reference)
#include <cuda_runtime.h>
#include <math.h>

#define CIN 48
#define CB  8
#define H   4096
#define HV  (H/4)          // 1024 float4 per channel row
#define NTHREADS 1024
#define NWARPS   (NTHREADS/32)
#define NPAIR    36        // upper-triangle incl. diag of 8x8
#define SCALE    0.35355339059327373f   // 1/sqrt(8)

__global__ __launch_bounds__(NTHREADS, 1)
void ultimus_kernel(const float* __restrict__ x,
                    const float* __restrict__ wd,   // [8,48]
                    const float* __restrict__ wu,   // [48,8]
                    float* __restrict__ out)
{
    __shared__ float s_wd[CB * CIN];          // 384
    __shared__ float s_gpart[NWARPS * NPAIR]; // 32*36 = 1152
    __shared__ float s_G[CB * CB];            // 64
    __shared__ float s_AM[CB * CB];           // 64
    __shared__ float s_W2[CIN * CB];          // 384, W2 = w_up @ am

    const int b    = blockIdx.x;
    const int t    = threadIdx.x;
    const int lane = t & 31;
    const int warp = t >> 5;

    if (t < CB * CIN) s_wd[t] = wd[t];
    __syncthreads();

    // ---------------- Pass 1: kqv = w_down @ x, kept in registers ----------
    const float4* __restrict__ x4 = (const float4*)(x + (size_t)b * CIN * H);

    float acc[CB][4];
    #pragma unroll
    for (int o = 0; o < CB; o++) {
        acc[o][0] = 0.f; acc[o][1] = 0.f; acc[o][2] = 0.f; acc[o][3] = 0.f;
    }

    #pragma unroll 4
    for (int c = 0; c < CIN; c++) {
        float4 xv = x4[c * HV + t];
        #pragma unroll
        for (int o = 0; o < CB; o++) {
            float w = s_wd[o * CIN + c];
            acc[o][0] += w * xv.x;
            acc[o][1] += w * xv.y;
            acc[o][2] += w * xv.z;
            acc[o][3] += w * xv.w;
        }
    }

    // ---------------- Gram: G[i][j] = sum_h kqv_i * kqv_j ------------------
    {
        int base = 0;
        #pragma unroll
        for (int i = 0; i < CB; i++) {
            #pragma unroll
            for (int j = i; j < CB; j++) {
                float s = acc[i][0] * acc[j][0] + acc[i][1] * acc[j][1]
                        + acc[i][2] * acc[j][2] + acc[i][3] * acc[j][3];
                #pragma unroll
                for (int off = 16; off > 0; off >>= 1)
                    s += __shfl_xor_sync(0xffffffffu, s, off);
                if (lane == 0) s_gpart[warp * NPAIR + base] = s;
                base++;
            }
        }
    }
    __syncthreads();

    // reduce 32 warp partials -> full symmetric G
    if (t < NPAIR) {
        float s = 0.f;
        #pragma unroll
        for (int w = 0; w < NWARPS; w++) s += s_gpart[w * NPAIR + t];
        // linear upper-tri index -> (i, j)
        int i = 0, rem = t;
        while (rem >= CB - i) { rem -= CB - i; i++; }
        int j = i + rem;
        s_G[i * CB + j] = s;
        s_G[j * CB + i] = s;
    }
    __syncthreads();

    // ---------------- Softmax rows of G*SCALE -> AM -------------------------
    if (t < CB) {
        float v[CB];
        float m = -1e30f;
        #pragma unroll
        for (int j = 0; j < CB; j++) {
            v[j] = s_G[t * CB + j] * SCALE;
            m = fmaxf(m, v[j]);
        }
        float sum = 0.f;
        #pragma unroll
        for (int j = 0; j < CB; j++) {
            v[j] = __expf(v[j] - m);
            sum += v[j];
        }
        float inv = 1.f / sum;
        #pragma unroll
        for (int j = 0; j < CB; j++) s_AM[t * CB + j] = v[j] * inv;
    }
    __syncthreads();

    // ---------------- W2[c][j] = sum_o wu[c][o] * AM[o][j] ------------------
    if (t < CIN * CB) {
        int c = t >> 3, j = t & 7;
        float s = 0.f;
        #pragma unroll
        for (int o = 0; o < CB; o++) s += wu[c * CB + o] * s_AM[o * CB + j];
        s_W2[c * CB + j] = s;
    }
    __syncthreads();

    // ---------------- Pass 2: out[c][h] = sum_j W2[c][j] * kqv[j][h] --------
    float4* __restrict__ out4 = (float4*)(out + (size_t)b * CIN * H);

    #pragma unroll 4
    for (int c = 0; c < CIN; c++) {
        const float4 w0 = ((const float4*)(s_W2 + c * CB))[0];
        const float4 w1 = ((const float4*)(s_W2 + c * CB))[1];
        float4 r;
        r.x = w0.x * acc[0][0] + w0.y * acc[1][0] + w0.z * acc[2][0] + w0.w * acc[3][0]
            + w1.x * acc[4][0] + w1.y * acc[5][0] + w1.z * acc[6][0] + w1.w * acc[7][0];
        r.y = w0.x * acc[0][1] + w0.y * acc[1][1] + w0.z * acc[2][1] + w0.w * acc[3][1]
            + w1.x * acc[4][1] + w1.y * acc[5][1] + w1.z * acc[6][1] + w1.w * acc[7][1];
        r.z = w0.x * acc[0][2] + w0.y * acc[1][2] + w0.z * acc[2][2] + w0.w * acc[3][2]
            + w1.x * acc[4][2] + w1.y * acc[5][2] + w1.z * acc[6][2] + w1.w * acc[7][2];
        r.w = w0.x * acc[0][3] + w0.y * acc[1][3] + w0.z * acc[2][3] + w0.w * acc[3][3]
            + w1.x * acc[4][3] + w1.y * acc[5][3] + w1.z * acc[6][3] + w1.w * acc[7][3];
        out4[c * HV + t] = r;
    }
}

extern "C" void kernel_launch(void* const* d_in, const int* in_sizes, int n_in,
                              void* d_out, int out_size)
{
    const float* x  = (const float*)d_in[0];   // [256, 48, 4096, 1]
    const float* wd = (const float*)d_in[1];   // [8, 48]
    const float* wu = (const float*)d_in[2];   // [48, 8]
    float* out = (float*)d_out;                // [256, 48, 4096, 1]

    ultimus_kernel<<<256, NTHREADS>>>(x, wd, wu, out);
}